// round 1
// baseline (speedup 1.0000x reference)
#include <cuda_runtime.h>

#define RMAX 32
#define SMAX 2
#define CZ   128               // channels
#define NPOS 66                // 2*(RMAX+1)
#define INDIM 139              // 2*NPOS + 1 + 2*(SMAX+1)

// shared: folded W table (139*128 floats) + packed per-j index array (N ints)
__global__ __launch_bounds__(1024, 2)
void relpos_kernel(const int* __restrict__ asym,
                   const int* __restrict__ resi,
                   const int* __restrict__ ent,
                   const int* __restrict__ sym,
                   const int* __restrict__ tok,
                   const float* __restrict__ W,
                   float* __restrict__ out,
                   int N)
{
    extern __shared__ float smem[];
    float* sW   = smem;                       // [INDIM*CZ]
    int*   sIdx = (int*)(smem + INDIM * CZ);  // [N]

    const int tid = threadIdx.x;
    const int i   = blockIdx.x;

    // Stage W into shared, folding  same_ent * w_ent  into W_ch rows 133..137.
    // (d_chain == 5  <=>  !same_ent, so rows 133..137 get +w_ent, row 138 does not.)
    for (int k = tid; k < INDIM * CZ; k += blockDim.x) {
        int row = k >> 7;               // /CZ
        float v = W[k];
        if (row >= 2 * NPOS + 1 && row < INDIM - 1)
            v += W[(2 * NPOS) * CZ + (k & (CZ - 1))];
        sW[k] = v;
    }

    const int ai = asym[i], ri = resi[i], ei = ent[i], si = sym[i], ti = tok[i];

    // Precompute packed (rowA | rowB<<8 | rowC<<20) for every j of this i-row.
    for (int j = tid; j < N; j += blockDim.x) {
        int aj = asym[j], rj = resi[j], ej = ent[j], sj = sym[j], tj = tok[j];
        bool sc = (ai == aj);
        bool sr = (ri == rj);
        bool se = (ei == ej);

        int dres = min(max(ri - rj + RMAX, 0), 2 * RMAX);
        if (!sc) dres = 2 * RMAX + 1;

        int dtok = min(max(ti - tj + RMAX, 0), 2 * RMAX);
        if (!(sc && sr)) dtok = 2 * RMAX + 1;

        int dch = min(max(si - sj + SMAX, 0), 2 * SMAX);
        if (!se) dch = 2 * SMAX + 1;

        sIdx[j] = dres | ((NPOS + dtok) << 8) | ((2 * NPOS + 1 + dch) << 20);
    }
    __syncthreads();

    const float4* sW4  = (const float4*)sW;
    float4*       out4 = (float4*)out;
    const int tx = tid & 31;     // float4 channel group: covers c = tx*4 .. tx*4+3
    const int ty = tid >> 5;     // which j this warp handles
    const size_t rowbase = (size_t)i * N;

    #pragma unroll 4
    for (int j = ty; j < N; j += 32) {
        int p  = sIdx[j];                 // uniform per warp (LDS broadcast)
        int rA = p & 0xFF;
        int rB = (p >> 8) & 0xFFF;
        int rC = (p >> 20);

        float4 a = sW4[rA * (CZ / 4) + tx];
        float4 b = sW4[rB * (CZ / 4) + tx];
        float4 c = sW4[rC * (CZ / 4) + tx];

        float4 s;
        s.x = a.x + b.x + c.x;
        s.y = a.y + b.y + c.y;
        s.z = a.z + b.z + c.z;
        s.w = a.w + b.w + c.w;

        out4[(rowbase + j) * (CZ / 4) + tx] = s;   // warp: 512B contiguous STG.128
    }
}

extern "C" void kernel_launch(void* const* d_in, const int* in_sizes, int n_in,
                              void* d_out, int out_size)
{
    const int*   asym = (const int*)d_in[0];
    const int*   resi = (const int*)d_in[1];
    const int*   ent  = (const int*)d_in[2];
    const int*   sym  = (const int*)d_in[3];
    const int*   tok  = (const int*)d_in[4];
    const float* W    = (const float*)d_in[5];
    float*       out  = (float*)d_out;

    const int N = in_sizes[0];                  // B*N with B==1 -> 1024
    const int smem_bytes = INDIM * CZ * (int)sizeof(float) + N * (int)sizeof(int);

    cudaFuncSetAttribute(relpos_kernel,
                         cudaFuncAttributeMaxDynamicSharedMemorySize, smem_bytes);

    relpos_kernel<<<N, 1024, smem_bytes>>>(asym, resi, ent, sym, tok, W, out, N);
}

// round 2
// speedup vs baseline: 1.4864x; 1.4864x over previous
#include <cuda_runtime.h>

#define RMAX 32
#define SMAX 2
#define CZ   128               // channels
#define NPOS 66                // 2*(RMAX+1)
#define NU   132               // combined pos/tok table rows
#define NROW 138               // NU + 6 chain rows

// Shared layout: folded tables (138*128 floats) + packed per-j index array (N ints)
//   U[d]     (d<66)  = W_pos[d]  + W_tok[65]      (case: same_chain, !same_res -> index d_res)
//   U[66+d]  (d<66)  = W_tok[d]  + W_pos[32]      (case: same_chain, same_res  -> index 66+d_tok)
//   (!same_chain -> U[65] = W_pos[65] + W_tok[65])
//   C[d]     (d<6)   = W_ch[d] + (d<5 ? w_ent : 0)
__global__ __launch_bounds__(1024, 2)
void relpos_kernel(const int* __restrict__ asym,
                   const int* __restrict__ resi,
                   const int* __restrict__ ent,
                   const int* __restrict__ sym,
                   const int* __restrict__ tok,
                   const float* __restrict__ W,
                   float* __restrict__ out,
                   int N)
{
    extern __shared__ float smem[];
    float* sW   = smem;                       // [NROW*CZ]
    int*   sIdx = (int*)(smem + NROW * CZ);   // [N]

    const int tid = threadIdx.x;
    const int i   = blockIdx.x;

    // Stage folded tables into shared.
    for (int k = tid; k < NROW * CZ; k += blockDim.x) {
        int row = k >> 7;            // /CZ
        int c   = k & (CZ - 1);
        float v;
        if (row < NPOS) {
            // U[row] = W_pos[row] + W_tok[65]
            v = W[row * CZ + c] + W[(NPOS + 65) * CZ + c];
        } else if (row < NU) {
            // U[66+d] = W_tok[d] + W_pos[32]
            v = W[(NPOS + (row - NPOS)) * CZ + c] + W[32 * CZ + c];
        } else {
            // C[d] = W_ch[d] + (d<5)*w_ent ; W_ch rows start at 133, w_ent at 132
            int d = row - NU;
            v = W[(2 * NPOS + 1 + d) * CZ + c];
            if (d < 5) v += W[(2 * NPOS) * CZ + c];
        }
        sW[k] = v;
    }

    const int ai = asym[i], ri = resi[i], ei = ent[i], si = sym[i], ti = tok[i];

    // Precompute packed (u | cRel<<8) for every j of this i-row.
    for (int j = tid; j < N; j += blockDim.x) {
        int aj = asym[j], rj = resi[j], ej = ent[j], sj = sym[j], tj = tok[j];
        bool sc = (ai == aj);
        bool sr = (ri == rj);
        bool se = (ei == ej);

        int u;
        if (sc && sr)       u = NPOS + min(max(ti - tj + RMAX, 0), 2 * RMAX);
        else if (sc)        u = min(max(ri - rj + RMAX, 0), 2 * RMAX);
        else                u = 2 * RMAX + 1;   // 65

        int cRel = se ? min(max(si - sj + SMAX, 0), 2 * SMAX) : (2 * SMAX + 1);

        sIdx[j] = u | (cRel << 8);
    }
    __syncthreads();

    const float4* sW4  = (const float4*)sW;
    float4*       out4 = (float4*)out;
    const int tx = tid & 31;     // float4 channel group: covers c = tx*4 .. tx*4+3
    const int ty = tid >> 5;     // which j this warp handles
    const size_t rowbase = (size_t)i * N;

    #pragma unroll 8
    for (int j = ty; j < N; j += 32) {
        int p  = sIdx[j];                 // uniform per warp (LDS broadcast)
        int rU = p & 0xFF;
        int rC = NU + (p >> 8);

        float4 a = sW4[rU * (CZ / 4) + tx];
        float4 c = sW4[rC * (CZ / 4) + tx];

        float4 s;
        s.x = a.x + c.x;
        s.y = a.y + c.y;
        s.z = a.z + c.z;
        s.w = a.w + c.w;

        out4[(rowbase + j) * (CZ / 4) + tx] = s;   // warp: 512B contiguous STG.128
    }
}

extern "C" void kernel_launch(void* const* d_in, const int* in_sizes, int n_in,
                              void* d_out, int out_size)
{
    const int*   asym = (const int*)d_in[0];
    const int*   resi = (const int*)d_in[1];
    const int*   ent  = (const int*)d_in[2];
    const int*   sym  = (const int*)d_in[3];
    const int*   tok  = (const int*)d_in[4];
    const float* W    = (const float*)d_in[5];
    float*       out  = (float*)d_out;

    const int N = in_sizes[0];                  // B*N with B==1 -> 1024
    const int smem_bytes = NROW * CZ * (int)sizeof(float) + N * (int)sizeof(int);

    cudaFuncSetAttribute(relpos_kernel,
                         cudaFuncAttributeMaxDynamicSharedMemorySize, smem_bytes);

    relpos_kernel<<<N, 1024, smem_bytes>>>(asym, resi, ent, sym, tok, W, out, N);
}

// round 3
// speedup vs baseline: 1.4951x; 1.0059x over previous
#include <cuda_runtime.h>

#define RMAX 32
#define SMAX 2
#define CZ   128               // channels
#define NPOS 66                // 2*(RMAX+1)
#define NU   132               // combined pos/tok table rows
#define NROW 138               // NU + 6 chain rows
#define NMAX 1024

// Folded tables in shared:
//   U[d]    (d<66) = W_pos[d] + W_tok[65]   (same_chain, !same_res -> index d_res)
//   U[66+d] (d<66) = W_tok[d] + W_pos[32]   (same_chain,  same_res -> index 66+d_tok)
//   (!same_chain -> U[65] = W_pos[65] + W_tok[65])
//   C[d]    (d<6)  = W_ch[d] + (d<5 ? w_ent : 0)
__global__ __launch_bounds__(1024, 2)
void relpos_kernel(const int* __restrict__ asym,
                   const int* __restrict__ resi,
                   const int* __restrict__ ent,
                   const int* __restrict__ sym,
                   const int* __restrict__ tok,
                   const float* __restrict__ W,
                   float* __restrict__ out,
                   int N)
{
    extern __shared__ float smem[];
    float* sW   = smem;                        // [NROW*CZ]
    int*   sIdx = (int*)(smem + NROW * CZ);    // [2][NMAX] double-buffered

    const int tid = threadIdx.x;

    // Stage folded tables into shared (once per CTA).
    for (int k = tid; k < NROW * CZ; k += blockDim.x) {
        int row = k >> 7;            // /CZ
        int c   = k & (CZ - 1);
        float v;
        if (row < NPOS) {
            v = W[row * CZ + c] + W[(NPOS + 65) * CZ + c];
        } else if (row < NU) {
            v = W[(NPOS + (row - NPOS)) * CZ + c] + W[32 * CZ + c];
        } else {
            int d = row - NU;
            v = W[(2 * NPOS + 1 + d) * CZ + c];
            if (d < 5) v += W[(2 * NPOS) * CZ + c];
        }
        sW[k] = v;
    }

    // Thread tid owns column j = tid: keep its quintuple in registers.
    int aj = 0, rj = 0, ej = 0, sj = 0, tj = 0;
    if (tid < N) {
        aj = asym[tid]; rj = resi[tid]; ej = ent[tid];
        sj = sym[tid];  tj = tok[tid];
    }

    const float4* sW4  = (const float4*)sW;
    float4*       out4 = (float4*)out;
    const int tx = tid & 31;     // channel group: c = tx*4 .. tx*4+3
    const int ty = tid >> 5;     // which j this warp handles

    int it = 0;
    for (int i = blockIdx.x; i < N; i += gridDim.x, ++it) {
        // Row scalars (L1-hit broadcast loads).
        const int ai = __ldg(&asym[i]), ri = __ldg(&resi[i]);
        const int ei = __ldg(&ent[i]),  si = __ldg(&sym[i]);
        const int ti = __ldg(&tok[i]);

        int* sI = sIdx + (it & 1) * NMAX;
        if (tid < N) {
            bool sc = (ai == aj);
            bool sr = (ri == rj);
            bool se = (ei == ej);

            int u;
            if (sc && sr)  u = NPOS + min(max(ti - tj + RMAX, 0), 2 * RMAX);
            else if (sc)   u = min(max(ri - rj + RMAX, 0), 2 * RMAX);
            else           u = 2 * RMAX + 1;

            int cRel = se ? min(max(si - sj + SMAX, 0), 2 * SMAX) : (2 * SMAX + 1);
            sI[tid] = u | (cRel << 8);
        }
        __syncthreads();   // sI ready; also guards prev-buffer reuse 2 iters later

        const size_t rowbase = (size_t)i * N;
        #pragma unroll 8
        for (int j = ty; j < N; j += 32) {
            int p  = sI[j];                 // uniform per warp (LDS broadcast)
            int rU = p & 0xFF;
            int rC = NU + (p >> 8);

            float4 a = sW4[rU * (CZ / 4) + tx];
            float4 c = sW4[rC * (CZ / 4) + tx];

            float4 s;
            s.x = a.x + c.x;
            s.y = a.y + c.y;
            s.z = a.z + c.z;
            s.w = a.w + c.w;

            // Streaming store: write-once data, keep it out of L2's working set.
            __stcs(&out4[(rowbase + j) * (CZ / 4) + tx], s);
        }
    }
}

extern "C" void kernel_launch(void* const* d_in, const int* in_sizes, int n_in,
                              void* d_out, int out_size)
{
    const int*   asym = (const int*)d_in[0];
    const int*   resi = (const int*)d_in[1];
    const int*   ent  = (const int*)d_in[2];
    const int*   sym  = (const int*)d_in[3];
    const int*   tok  = (const int*)d_in[4];
    const float* W    = (const float*)d_in[5];
    float*       out  = (float*)d_out;

    const int N = in_sizes[0];                  // B*N with B==1 -> 1024

    int nsm = 148;
    cudaDeviceGetAttribute(&nsm, cudaDevAttrMultiProcessorCount, 0);
    int grid = 2 * nsm;
    if (grid > N) grid = N;

    const int smem_bytes = NROW * CZ * (int)sizeof(float)
                         + 2 * NMAX * (int)sizeof(int);

    cudaFuncSetAttribute(relpos_kernel,
                         cudaFuncAttributeMaxDynamicSharedMemorySize, smem_bytes);

    relpos_kernel<<<grid, 1024, smem_bytes>>>(asym, resi, ent, sym, tok, W, out, N);
}